// round 1
// baseline (speedup 1.0000x reference)
#include <cuda_runtime.h>
#include <math.h>

#define C_   256
#define HW_  4096
#define B_   2
#define NH_  8
#define DH_  32
#define LOG2E 1.4426950408889634f

// Scratch (no cudaMalloc allowed): q, k, v, attn-out, each [B, C, HW] fp32 = 8MB
__device__ float g_q[B_ * C_ * HW_];
__device__ float g_k[B_ * C_ * HW_];
__device__ float g_v[B_ * C_ * HW_];
__device__ float g_attn[B_ * C_ * HW_];

// ---------------------------------------------------------------------------
// Projection GEMM: dst[b,o,n] = W[o,:] @ src[b,:,n] + bias[o]
// If resid != null: dst = gamma * (acc + bias) + resid   (final output proj)
// M = C_ (o), N = HW_ (n), K = C_ (c). Tiles 64x64x16, 4x4 micro-tiles.
// ---------------------------------------------------------------------------
__global__ __launch_bounds__(256) void proj_kernel(
    const float* __restrict__ W, const float* __restrict__ bias,
    const float* __restrict__ src, float* __restrict__ dst,
    const float* __restrict__ resid, const float* __restrict__ gamma)
{
    __shared__ float As[16][68];   // [k][m], padded (16B-aligned rows)
    __shared__ float Bs[16][64];   // [k][n]

    const int b  = blockIdx.z;
    const int n0 = blockIdx.x << 6;
    const int m0 = blockIdx.y << 6;
    const int t  = threadIdx.x;
    const int tm = t >> 4, tn = t & 15;

    const float* srcb = src + (size_t)b * C_ * HW_;

    const int am = t >> 2;          // 0..63 (row of A tile)
    const int ak = (t & 3) << 2;    // 0,4,8,12
    const int bk = t >> 4;          // 0..15 (row of B tile)
    const int bn = (t & 15) << 2;   // 0..60

    float acc[4][4] = {};

    for (int k0 = 0; k0 < C_; k0 += 16) {
        // A: W[m0+am][k0+ak..+4] -> As[k][m] (transposed store)
        float4 a = *(const float4*)&W[(size_t)(m0 + am) * C_ + k0 + ak];
        As[ak + 0][am] = a.x; As[ak + 1][am] = a.y;
        As[ak + 2][am] = a.z; As[ak + 3][am] = a.w;
        // B: src[b][k0+bk][n0+bn..+4] -> Bs[k][n] (coalesced)
        *(float4*)&Bs[bk][bn] =
            *(const float4*)&srcb[(size_t)(k0 + bk) * HW_ + n0 + bn];
        __syncthreads();

        #pragma unroll
        for (int k = 0; k < 16; k++) {
            float4 a4 = *(const float4*)&As[k][tm << 2];
            float4 b4 = *(const float4*)&Bs[k][tn << 2];
            float av[4] = {a4.x, a4.y, a4.z, a4.w};
            float bv[4] = {b4.x, b4.y, b4.z, b4.w};
            #pragma unroll
            for (int i = 0; i < 4; i++)
                #pragma unroll
                for (int j = 0; j < 4; j++)
                    acc[i][j] += av[i] * bv[j];
        }
        __syncthreads();
    }

    const float g = resid ? gamma[0] : 0.0f;
    #pragma unroll
    for (int i = 0; i < 4; i++) {
        const int o = m0 + (tm << 2) + i;
        const float bia = bias[o];
        const size_t idx = ((size_t)b * C_ + o) * HW_ + n0 + (tn << 2);
        float4 r;
        if (resid) {
            float4 rr = *(const float4*)&resid[idx];
            r.x = g * (acc[i][0] + bia) + rr.x;
            r.y = g * (acc[i][1] + bia) + rr.y;
            r.z = g * (acc[i][2] + bia) + rr.z;
            r.w = g * (acc[i][3] + bia) + rr.w;
        } else {
            r.x = acc[i][0] + bia; r.y = acc[i][1] + bia;
            r.z = acc[i][2] + bia; r.w = acc[i][3] + bia;
        }
        *(float4*)&dst[idx] = r;
    }
}

// ---------------------------------------------------------------------------
// Fused flash attention, one (b,h) slice per blockIdx.y, 64-query tile per
// blockIdx.x. q/k/v global layout: [bh][d=32][HW]. Output same layout.
// ---------------------------------------------------------------------------
__global__ __launch_bounds__(256) void attn_kernel(
    const float* __restrict__ q, const float* __restrict__ k,
    const float* __restrict__ v, float* __restrict__ o)
{
    __shared__ float qs[32][64];     // [d][q]
    __shared__ float ks[32][64];     // [d][m]
    __shared__ float vs[64][33];     // [m][d]  (transposed on load, pad 33)
    __shared__ float Ps[64][65];     // scores / probs [q][m], pad 65
    __shared__ float alphas[64];
    __shared__ float Ls[64];

    const int bh = blockIdx.y;          // b*8 + h
    const int q0 = blockIdx.x << 6;
    const int t  = threadIdx.x;
    const size_t base = (size_t)bh * DH_ * HW_;
    const float* qb = q + base;
    const float* kb = k + base;
    const float* vb = v + base;

    // tile-load mappings
    const int ld_d = t >> 3;            // 0..31
    const int ld_c = (t & 7) << 3;      // 0..56 step 8
    const int tv_c = t & 63;            // 0..63
    const int tv_d = t >> 6;            // 0..3
    // S micro-tile mapping
    const int tm = t >> 4, tn = t & 15;
    // softmax row mapping (quad per row)
    const int qrow = t >> 2, qr = t & 3;
    // PV mapping: rows 4*qg.., cols 4*dg.., m-half
    const int qg = t & 15;
    const int dg = (t >> 4) & 7;
    const int half = t >> 7;

    // load q tile (persistent)
    #pragma unroll
    for (int j = 0; j < 8; j += 4)
        *(float4*)&qs[ld_d][ld_c + j] =
            *(const float4*)&qb[(size_t)ld_d * HW_ + q0 + ld_c + j];

    float M = -INFINITY, L = 0.0f;
    float acc[4][4] = {};
    __syncthreads();

    for (int m0 = 0; m0 < HW_; m0 += 64) {
        // ---- load k tile [d][m] (direct) and v tile transposed -> [m][d]
        #pragma unroll
        for (int j = 0; j < 8; j += 4)
            *(float4*)&ks[ld_d][ld_c + j] =
                *(const float4*)&kb[(size_t)ld_d * HW_ + m0 + ld_c + j];
        #pragma unroll
        for (int i = 0; i < 8; i++) {
            const int d = (i << 2) + tv_d;
            vs[tv_c][d] = vb[(size_t)d * HW_ + m0 + tv_c];
        }
        __syncthreads();

        // ---- S = q^T k, 4x4 micro-tile per thread
        float s[4][4] = {};
        #pragma unroll
        for (int d = 0; d < 32; d++) {
            float4 a4 = *(const float4*)&qs[d][tm << 2];
            float4 b4 = *(const float4*)&ks[d][tn << 2];
            float av[4] = {a4.x, a4.y, a4.z, a4.w};
            float bv[4] = {b4.x, b4.y, b4.z, b4.w};
            #pragma unroll
            for (int i = 0; i < 4; i++)
                #pragma unroll
                for (int j = 0; j < 4; j++)
                    s[i][j] += av[i] * bv[j];
        }
        #pragma unroll
        for (int i = 0; i < 4; i++)
            #pragma unroll
            for (int j = 0; j < 4; j++)
                Ps[(tm << 2) + i][(tn << 2) + j] = s[i][j];
        // row q's writer warp == row q's softmax warp (both = warp q/8)
        __syncwarp();

        // ---- online softmax, 4 threads per row
        float rmax = -INFINITY;
        #pragma unroll
        for (int jj = 0; jj < 16; jj++)
            rmax = fmaxf(rmax, Ps[qrow][qr + (jj << 2)]);
        rmax = fmaxf(rmax, __shfl_xor_sync(0xffffffffu, rmax, 1));
        rmax = fmaxf(rmax, __shfl_xor_sync(0xffffffffu, rmax, 2));
        const float mnew  = fmaxf(M, rmax);
        const float alpha = exp2f((M - mnew) * LOG2E);
        float rsum = 0.0f;
        #pragma unroll
        for (int jj = 0; jj < 16; jj++) {
            const float p = exp2f((Ps[qrow][qr + (jj << 2)] - mnew) * LOG2E);
            Ps[qrow][qr + (jj << 2)] = p;
            rsum += p;
        }
        rsum += __shfl_xor_sync(0xffffffffu, rsum, 1);
        rsum += __shfl_xor_sync(0xffffffffu, rsum, 2);
        L = L * alpha + rsum;
        M = mnew;
        if (qr == 0) alphas[qrow] = alpha;
        __syncthreads();

        // ---- PV: acc[4q][4d] over this thread's m-half
        float al[4];
        #pragma unroll
        for (int i = 0; i < 4; i++) al[i] = alphas[(qg << 2) + i];
        #pragma unroll
        for (int i = 0; i < 4; i++)
            #pragma unroll
            for (int j = 0; j < 4; j++)
                acc[i][j] *= al[i];

        const int mbase = half << 5;
        #pragma unroll 4
        for (int mm = 0; mm < 32; mm++) {
            const int m = mbase + mm;
            const float pv0 = Ps[(qg << 2) + 0][m];
            const float pv1 = Ps[(qg << 2) + 1][m];
            const float pv2 = Ps[(qg << 2) + 2][m];
            const float pv3 = Ps[(qg << 2) + 3][m];
            #pragma unroll
            for (int j = 0; j < 4; j++) {
                const float vv = vs[m][(dg << 2) + j];
                acc[0][j] += pv0 * vv;
                acc[1][j] += pv1 * vv;
                acc[2][j] += pv2 * vv;
                acc[3][j] += pv3 * vv;
            }
        }
        __syncthreads();
    }

    if (qr == 0) Ls[qrow] = L;
    __syncthreads();

    // combine m-halves into Ps reused as os[32][65]  (os[d][q])
    float* osf = &Ps[0][0];
    if (half == 0) {
        #pragma unroll
        for (int i = 0; i < 4; i++)
            #pragma unroll
            for (int j = 0; j < 4; j++)
                osf[((dg << 2) + j) * 65 + (qg << 2) + i] = acc[i][j];
    }
    __syncthreads();
    if (half == 1) {
        #pragma unroll
        for (int i = 0; i < 4; i++)
            #pragma unroll
            for (int j = 0; j < 4; j++)
                osf[((dg << 2) + j) * 65 + (qg << 2) + i] += acc[i][j];
    }
    __syncthreads();

    // coalesced store: for each d-row, 64 contiguous q
    const float invl = 1.0f / Ls[tv_c];
    #pragma unroll
    for (int i = 0; i < 8; i++) {
        const int d = (i << 2) + tv_d;
        o[base + (size_t)d * HW_ + q0 + tv_c] = osf[d * 65 + tv_c] * invl;
    }
}

// ---------------------------------------------------------------------------
extern "C" void kernel_launch(void* const* d_in, const int* in_sizes, int n_in,
                              void* d_out, int out_size)
{
    const float* x     = (const float*)d_in[0];
    const float* Wq    = (const float*)d_in[1];
    const float* bq    = (const float*)d_in[2];
    const float* Wk    = (const float*)d_in[3];
    const float* bk    = (const float*)d_in[4];
    const float* Wv    = (const float*)d_in[5];
    const float* bv    = (const float*)d_in[6];
    const float* Wo    = (const float*)d_in[7];
    const float* bo    = (const float*)d_in[8];
    const float* gamma = (const float*)d_in[9];
    float* out = (float*)d_out;

    float *qp, *kp, *vp, *ap;
    cudaGetSymbolAddress((void**)&qp, g_q);
    cudaGetSymbolAddress((void**)&kp, g_k);
    cudaGetSymbolAddress((void**)&vp, g_v);
    cudaGetSymbolAddress((void**)&ap, g_attn);

    dim3 pg(HW_ / 64, C_ / 64, B_);   // 64 x 4 x 2
    proj_kernel<<<pg, 256>>>(Wq, bq, x, qp, nullptr, nullptr);
    proj_kernel<<<pg, 256>>>(Wk, bk, x, kp, nullptr, nullptr);
    proj_kernel<<<pg, 256>>>(Wv, bv, x, vp, nullptr, nullptr);

    dim3 ag(HW_ / 64, B_ * NH_);      // 64 x 16
    attn_kernel<<<ag, 256>>>(qp, kp, vp, ap);

    proj_kernel<<<pg, 256>>>(Wo, bo, ap, out, x, gamma);
}

// round 3
// speedup vs baseline: 3.2586x; 3.2586x over previous
#include <cuda_runtime.h>
#include <cuda_bf16.h>
#include <math.h>
#include <stdint.h>

#define C_   256
#define HW_  4096
#define B_   2
#define NH_  8
#define DH_  32
#define LOG2E 1.4426950408889634f

// Scratch (no cudaMalloc): bf16 hi/lo planes for q,k,v + fp32 attention output
__device__ __nv_bfloat16 g_qh[B_ * C_ * HW_];
__device__ __nv_bfloat16 g_ql[B_ * C_ * HW_];
__device__ __nv_bfloat16 g_kh[B_ * C_ * HW_];
__device__ __nv_bfloat16 g_kl[B_ * C_ * HW_];
__device__ __nv_bfloat16 g_vh[B_ * C_ * HW_];
__device__ __nv_bfloat16 g_vl[B_ * C_ * HW_];
__device__ float g_attn[B_ * C_ * HW_];
__device__ float g_maxk[B_ * NH_];

// ===========================================================================
// helpers
// ===========================================================================
__device__ __forceinline__ uint32_t smem_u32(const void* p) {
    uint32_t a;
    asm("{ .reg .u64 t; cvta.to.shared.u64 t, %1; cvt.u32.u64 %0, t; }"
        : "=r"(a) : "l"(p));
    return a;
}
__device__ __forceinline__ void cp16(uint32_t saddr, const void* gaddr) {
    asm volatile("cp.async.cg.shared.global [%0], [%1], 16;"
                 :: "r"(saddr), "l"(gaddr));
}
#define CP_COMMIT() asm volatile("cp.async.commit_group;")
#define CP_WAIT(N)  asm volatile("cp.async.wait_group %0;" :: "n"(N))

__device__ __forceinline__ void ldsm_x4_t(uint32_t a[4], uint32_t addr) {
    asm volatile("ldmatrix.sync.aligned.m8n8.x4.trans.shared.b16 {%0,%1,%2,%3}, [%4];"
                 : "=r"(a[0]), "=r"(a[1]), "=r"(a[2]), "=r"(a[3]) : "r"(addr));
}
__device__ __forceinline__ void ldsm_x2_t(uint32_t& b0, uint32_t& b1, uint32_t addr) {
    asm volatile("ldmatrix.sync.aligned.m8n8.x2.trans.shared.b16 {%0,%1}, [%2];"
                 : "=r"(b0), "=r"(b1) : "r"(addr));
}
__device__ __forceinline__ void ldsm_x2(uint32_t& b0, uint32_t& b1, uint32_t addr) {
    asm volatile("ldmatrix.sync.aligned.m8n8.x2.shared.b16 {%0,%1}, [%2];"
                 : "=r"(b0), "=r"(b1) : "r"(addr));
}
__device__ __forceinline__ void mma_bf16(float c[4], const uint32_t a[4],
                                         uint32_t b0, uint32_t b1) {
    asm volatile("mma.sync.aligned.m16n8k16.row.col.f32.bf16.bf16.f32 "
                 "{%0,%1,%2,%3}, {%4,%5,%6,%7}, {%8,%9}, {%0,%1,%2,%3};"
                 : "+f"(c[0]), "+f"(c[1]), "+f"(c[2]), "+f"(c[3])
                 : "r"(a[0]), "r"(a[1]), "r"(a[2]), "r"(a[3]), "r"(b0), "r"(b1));
}
__device__ __forceinline__ float fexp2(float x) {
    float y; asm("ex2.approx.f32 %0, %1;" : "=f"(y) : "f"(x)); return y;
}
// pack (lo element, hi element) -> bf16x2 (lo in low 16 bits)
__device__ __forceinline__ uint32_t packbf(float lo, float hi) {
    uint32_t u; asm("cvt.rn.bf16x2.f32 %0, %1, %2;" : "=r"(u) : "f"(hi), "f"(lo));
    return u;
}
__device__ __forceinline__ void split1(float f, __nv_bfloat16& h, __nv_bfloat16& l) {
    h = __float2bfloat16_rn(f);
    l = __float2bfloat16_rn(f - __bfloat162float(h));
}

// ===========================================================================
// Projection GEMM: dst = W @ src + bias. Optionally writes bf16 hi/lo planes
// (for q,k,v) and/or fp32 with residual (final output projection).
// ===========================================================================
__global__ __launch_bounds__(256) void proj_kernel(
    const float* __restrict__ W, const float* __restrict__ bias,
    const float* __restrict__ src, float* __restrict__ dstf,
    __nv_bfloat16* __restrict__ dsth, __nv_bfloat16* __restrict__ dstl,
    const float* __restrict__ resid, const float* __restrict__ gamma)
{
    __shared__ float As[16][68];
    __shared__ float Bs[16][64];

    const int b  = blockIdx.z;
    const int n0 = blockIdx.x << 6;
    const int m0 = blockIdx.y << 6;
    const int t  = threadIdx.x;
    const int tm = t >> 4, tn = t & 15;
    const float* srcb = src + (size_t)b * C_ * HW_;
    const int am = t >> 2, ak = (t & 3) << 2;
    const int bk = t >> 4, bn = (t & 15) << 2;
    float acc[4][4] = {};

    for (int k0 = 0; k0 < C_; k0 += 16) {
        float4 a = *(const float4*)&W[(size_t)(m0 + am) * C_ + k0 + ak];
        As[ak + 0][am] = a.x; As[ak + 1][am] = a.y;
        As[ak + 2][am] = a.z; As[ak + 3][am] = a.w;
        *(float4*)&Bs[bk][bn] =
            *(const float4*)&srcb[(size_t)(k0 + bk) * HW_ + n0 + bn];
        __syncthreads();
        #pragma unroll
        for (int k = 0; k < 16; k++) {
            float4 a4 = *(const float4*)&As[k][tm << 2];
            float4 b4 = *(const float4*)&Bs[k][tn << 2];
            float av[4] = {a4.x, a4.y, a4.z, a4.w};
            float bv[4] = {b4.x, b4.y, b4.z, b4.w};
            #pragma unroll
            for (int i = 0; i < 4; i++)
                #pragma unroll
                for (int j = 0; j < 4; j++)
                    acc[i][j] += av[i] * bv[j];
        }
        __syncthreads();
    }
    const float g = resid ? gamma[0] : 0.0f;
    #pragma unroll
    for (int i = 0; i < 4; i++) {
        const int o = m0 + (tm << 2) + i;
        const float bia = bias[o];
        const size_t idx = ((size_t)b * C_ + o) * HW_ + n0 + (tn << 2);
        float f[4];
        #pragma unroll
        for (int j = 0; j < 4; j++) f[j] = acc[i][j] + bia;
        if (dsth) {
            __nv_bfloat16 h[4], l[4];
            #pragma unroll
            for (int j = 0; j < 4; j++) split1(f[j], h[j], l[j]);
            *(__nv_bfloat162*)&dsth[idx]     = __nv_bfloat162(h[0], h[1]);
            *(__nv_bfloat162*)&dsth[idx + 2] = __nv_bfloat162(h[2], h[3]);
            *(__nv_bfloat162*)&dstl[idx]     = __nv_bfloat162(l[0], l[1]);
            *(__nv_bfloat162*)&dstl[idx + 2] = __nv_bfloat162(l[2], l[3]);
        }
        if (dstf) {
            float4 r;
            if (resid) {
                float4 rr = *(const float4*)&resid[idx];
                r.x = g * f[0] + rr.x; r.y = g * f[1] + rr.y;
                r.z = g * f[2] + rr.z; r.w = g * f[3] + rr.w;
            } else {
                r.x = f[0]; r.y = f[1]; r.z = f[2]; r.w = f[3];
            }
            *(float4*)&dstf[idx] = r;
        }
    }
}

// ===========================================================================
// max ||k_m|| per (b,h), from bf16 planes (the K actually used by the MMA)
// ===========================================================================
__global__ __launch_bounds__(256) void maxk_kernel(
    const __nv_bfloat16* __restrict__ kh, const __nv_bfloat16* __restrict__ kl)
{
    __shared__ float red[256];
    const int bh = blockIdx.x;
    const int t = threadIdx.x;
    const size_t base = (size_t)bh * DH_ * HW_;
    float mx = 0.0f;
    for (int m = t; m < HW_; m += 256) {
        float s = 0.0f;
        #pragma unroll
        for (int d = 0; d < DH_; d++) {
            const size_t idx = base + (size_t)d * HW_ + m;
            float v = __bfloat162float(kh[idx]) + __bfloat162float(kl[idx]);
            s += v * v;
        }
        mx = fmaxf(mx, s);
    }
    red[t] = mx;
    __syncthreads();
    for (int o = 128; o > 0; o >>= 1) {
        if (t < o) red[t] = fmaxf(red[t], red[t + o]);
        __syncthreads();
    }
    if (t == 0) g_maxk[bh] = sqrtf(red[0]);
}

// ===========================================================================
// HMMA flash attention. CTA = 128 queries of one (b,h); 8 warps; Bc = 64.
// Smem layout (dynamic):
//   sQ : 2 planes x [32 d][136]   bf16  (rows 272B, +16B pad -> ldmatrix ok)
//   sK : 2 bufs x 2 planes x [32 d][72]  bf16 (rows 144B)
//   sV : same
//   mhat[128] fp32 (pre-multiplied by LOG2E)
// ===========================================================================
#define SQ_OFF 0
#define SQ_ROW 136
#define SK_OFF (SQ_OFF + 2 * 32 * SQ_ROW * 2)          // 17408
#define KV_ROW 72
#define KV_PLANE (32 * KV_ROW * 2)                     // 4608
#define KV_BUF   (2 * KV_PLANE)                        // 9216
#define SV_OFF (SK_OFF + 2 * KV_BUF)                   // 35840
#define MH_OFF (SV_OFF + 2 * KV_BUF)                   // 54272
#define SMEM_TOTAL (MH_OFF + 128 * 4)                  // 54784

__global__ __launch_bounds__(256, 2) void attn_mma_kernel(
    const __nv_bfloat16* __restrict__ qh, const __nv_bfloat16* __restrict__ ql,
    const __nv_bfloat16* __restrict__ kh, const __nv_bfloat16* __restrict__ kl,
    const __nv_bfloat16* __restrict__ vh, const __nv_bfloat16* __restrict__ vl,
    float* __restrict__ o)
{
    extern __shared__ char smem[];
    const uint32_t sb = smem_u32(smem);
    float* mhat = (float*)(smem + MH_OFF);

    const int bh = blockIdx.y;
    const int q0 = blockIdx.x << 7;
    const int t  = threadIdx.x;
    const int w  = t >> 5;
    const int lane = t & 31;
    const int g  = lane >> 2;       // mma group row
    const int tq = lane & 3;        // thread-in-group
    const size_t base = (size_t)bh * DH_ * HW_;

    // ---- issue Q (both planes) + KV iter 0 into buf 0
    {
        const __nv_bfloat16* qp[2] = { qh + base, ql + base };
        #pragma unroll
        for (int i = 0; i < 4; i++) {
            const int idx = t + (i << 8);            // 0..1023
            const int p = idx >> 9, d = (idx >> 4) & 31, c = idx & 15;
            cp16(sb + SQ_OFF + (p * 32 + d) * (SQ_ROW * 2) + c * 16,
                 qp[p] + (size_t)d * HW_ + q0 + c * 8);
        }
        const __nv_bfloat16* kvp[4] = { kh + base, kl + base, vh + base, vl + base };
        #pragma unroll
        for (int i = 0; i < 4; i++) {
            const int idx = t + (i << 8);            // 0..1023
            const int tp = idx >> 8;                 // 0..3 (kh,kl,vh,vl)
            const int d = (idx >> 3) & 31, c = idx & 7;
            const uint32_t so = (tp < 2 ? SK_OFF : SV_OFF) + ((tp & 1) * KV_PLANE);
            cp16(sb + so + d * (KV_ROW * 2) + c * 16,
                 kvp[tp] + (size_t)d * HW_ + c * 8);
        }
        CP_COMMIT();
    }
    CP_WAIT(0);
    __syncthreads();

    // ---- mhat rows (pre-scaled by LOG2E)
    if (t < 128) {
        float s = 0.0f;
        #pragma unroll
        for (int d = 0; d < DH_; d++) {
            const __nv_bfloat16* qr =
                (const __nv_bfloat16*)(smem + SQ_OFF + d * (SQ_ROW * 2));
            const __nv_bfloat16* qr2 =
                (const __nv_bfloat16*)(smem + SQ_OFF + (32 + d) * (SQ_ROW * 2));
            float f = __bfloat162float(qr[t]) + __bfloat162float(qr2[t]);
            s += f * f;
        }
        mhat[t] = sqrtf(s) * g_maxk[bh] * LOG2E;
    }

    // ---- Q fragments (persist): aQ[plane][kstep][4]
    uint32_t aQ[2][2][4];
    {
        const int qw = w << 4;
        const int qrow = (lane & 7) + ((lane >> 4) << 3);       // d within tile
        const int qcol = qw + (((lane >> 3) & 1) << 3);         // q within tile
        #pragma unroll
        for (int p = 0; p < 2; p++)
            #pragma unroll
            for (int s = 0; s < 2; s++)
                ldsm_x4_t(aQ[p][s],
                    sb + SQ_OFF + (p * 32 + (s << 4) + qrow) * (SQ_ROW * 2)
                       + qcol * 2);
    }
    __syncthreads();   // mhat visible

    const float mh0 = mhat[(w << 4) + g];
    const float mh1 = mhat[(w << 4) + g + 8];

    float oacc[4][4] = {};
    float Lac0 = 0.0f, Lac1 = 0.0f;

    const int kRow = lane & 15;                       // trans ldmatrix row
    const int vRow = lane & 7;                        // non-trans row
    const int vCol = ((lane >> 3) & 1) << 3;

    const __nv_bfloat16* kvp[4] = { kh + base, kl + base, vh + base, vl + base };

    for (int i = 0; i < 64; i++) {
        const uint32_t bufC = (uint32_t)(i & 1) * KV_BUF;
        // ---- prefetch next KV into alternate buffer
        if (i < 63) {
            const int m0n = (i + 1) << 6;
            const uint32_t bufN = (uint32_t)((i + 1) & 1) * KV_BUF;
            #pragma unroll
            for (int u = 0; u < 4; u++) {
                const int idx = t + (u << 8);
                const int tp = idx >> 8;
                const int d = (idx >> 3) & 31, c = idx & 7;
                const uint32_t so = (tp < 2 ? SK_OFF : SV_OFF)
                                  + ((tp & 1) * KV_PLANE) + bufN;
                cp16(sb + so + d * (KV_ROW * 2) + c * 16,
                     kvp[tp] + (size_t)d * HW_ + m0n + c * 8);
            }
            CP_COMMIT();
            CP_WAIT(1);
        } else {
            CP_WAIT(0);
        }
        __syncthreads();

        // ---- S = Q K^T (3-term bf16 split): sacc[8 nblk][4]
        float sacc[8][4];
        #pragma unroll
        for (int j = 0; j < 8; j++)
            #pragma unroll
            for (int e = 0; e < 4; e++) sacc[j][e] = 0.0f;

        #pragma unroll
        for (int s = 0; s < 2; s++) {
            const uint32_t ka = sb + SK_OFF + bufC
                              + ((s << 4) + kRow) * (KV_ROW * 2);
            #pragma unroll
            for (int j = 0; j < 8; j++) {
                uint32_t bh0, bh1, bl0, bl1;
                ldsm_x2_t(bh0, bh1, ka + (j << 4));
                ldsm_x2_t(bl0, bl1, ka + KV_PLANE + (j << 4));
                mma_bf16(sacc[j], aQ[0][s], bh0, bh1);   // qh*kh
                mma_bf16(sacc[j], aQ[1][s], bh0, bh1);   // ql*kh
                mma_bf16(sacc[j], aQ[0][s], bl0, bl1);   // qh*kl
            }
        }

        // ---- softmax (fixed bound, no rescale), P stays in registers
        #pragma unroll
        for (int j = 0; j < 8; j++) {
            sacc[j][0] = fexp2(fmaf(sacc[j][0], LOG2E, -mh0));
            sacc[j][1] = fexp2(fmaf(sacc[j][1], LOG2E, -mh0));
            sacc[j][2] = fexp2(fmaf(sacc[j][2], LOG2E, -mh1));
            sacc[j][3] = fexp2(fmaf(sacc[j][3], LOG2E, -mh1));
            Lac0 += sacc[j][0] + sacc[j][1];
            Lac1 += sacc[j][2] + sacc[j][3];
        }

        // ---- O += P V (3-term split)
        #pragma unroll
        for (int s = 0; s < 4; s++) {
            uint32_t ah[4], al[4];
            ah[0] = packbf(sacc[2*s][0],   sacc[2*s][1]);
            ah[1] = packbf(sacc[2*s][2],   sacc[2*s][3]);
            ah[2] = packbf(sacc[2*s+1][0], sacc[2*s+1][1]);
            ah[3] = packbf(sacc[2*s+1][2], sacc[2*s+1][3]);
            #pragma unroll
            for (int e = 0; e < 4; e++) {
                const float* pp = (e < 2) ? sacc[2*s] : sacc[2*s+1];
                const int b0i = (e & 1) << 1;
                const float hx = __uint_as_float(ah[e] << 16);
                const float hy = __uint_as_float(ah[e] & 0xffff0000u);
                al[e] = packbf(pp[b0i] - hx, pp[b0i + 1] - hy);
            }
            const uint32_t va = sb + SV_OFF + bufC + vRow * (KV_ROW * 2)
                              + ((s << 4) + vCol) * 2;
            #pragma unroll
            for (int j = 0; j < 4; j++) {
                uint32_t bh0, bh1, bl0, bl1;
                ldsm_x2(bh0, bh1, va + (j << 3) * (KV_ROW * 2));
                ldsm_x2(bl0, bl1, va + KV_PLANE + (j << 3) * (KV_ROW * 2));
                mma_bf16(oacc[j], ah, bh0, bh1);   // ph*vh
                mma_bf16(oacc[j], al, bh0, bh1);   // pl*vh
                mma_bf16(oacc[j], ah, bl0, bl1);   // ph*vl
            }
        }
        __syncthreads();
    }

    // ---- epilogue: reduce L over the quad, normalize, store
    Lac0 += __shfl_xor_sync(0xffffffffu, Lac0, 1);
    Lac0 += __shfl_xor_sync(0xffffffffu, Lac0, 2);
    Lac1 += __shfl_xor_sync(0xffffffffu, Lac1, 1);
    Lac1 += __shfl_xor_sync(0xffffffffu, Lac1, 2);
    const float inv0 = 1.0f / Lac0;
    const float inv1 = 1.0f / Lac1;

    const int r0 = q0 + (w << 4) + g;
    const int r1 = r0 + 8;
    #pragma unroll
    for (int j = 0; j < 4; j++) {
        const int d = (j << 3) + (tq << 1);
        o[base + (size_t)d * HW_ + r0]       = oacc[j][0] * inv0;
        o[base + (size_t)(d + 1) * HW_ + r0] = oacc[j][1] * inv0;
        o[base + (size_t)d * HW_ + r1]       = oacc[j][2] * inv1;
        o[base + (size_t)(d + 1) * HW_ + r1] = oacc[j][3] * inv1;
    }
}

// ===========================================================================
extern "C" void kernel_launch(void* const* d_in, const int* in_sizes, int n_in,
                              void* d_out, int out_size)
{
    const float* x     = (const float*)d_in[0];
    const float* Wq    = (const float*)d_in[1];
    const float* bq    = (const float*)d_in[2];
    const float* Wk    = (const float*)d_in[3];
    const float* bk    = (const float*)d_in[4];
    const float* Wv    = (const float*)d_in[5];
    const float* bv    = (const float*)d_in[6];
    const float* Wo    = (const float*)d_in[7];
    const float* bo    = (const float*)d_in[8];
    const float* gamma = (const float*)d_in[9];
    float* out = (float*)d_out;

    __nv_bfloat16 *qhp, *qlp, *khp, *klp, *vhp, *vlp;
    float *ap;
    cudaGetSymbolAddress((void**)&qhp, g_qh);
    cudaGetSymbolAddress((void**)&qlp, g_ql);
    cudaGetSymbolAddress((void**)&khp, g_kh);
    cudaGetSymbolAddress((void**)&klp, g_kl);
    cudaGetSymbolAddress((void**)&vhp, g_vh);
    cudaGetSymbolAddress((void**)&vlp, g_vl);
    cudaGetSymbolAddress((void**)&ap, g_attn);

    cudaFuncSetAttribute(attn_mma_kernel,
                         cudaFuncAttributeMaxDynamicSharedMemorySize, SMEM_TOTAL);

    dim3 pg(HW_ / 64, C_ / 64, B_);
    proj_kernel<<<pg, 256>>>(Wq, bq, x, nullptr, qhp, qlp, nullptr, nullptr);
    proj_kernel<<<pg, 256>>>(Wk, bk, x, nullptr, khp, klp, nullptr, nullptr);
    proj_kernel<<<pg, 256>>>(Wv, bv, x, nullptr, vhp, vlp, nullptr, nullptr);

    maxk_kernel<<<B_ * NH_, 256>>>(khp, klp);

    dim3 ag(HW_ / 128, B_ * NH_);     // 32 x 16
    attn_mma_kernel<<<ag, 256, SMEM_TOTAL>>>(qhp, qlp, khp, klp, vhp, vlp, ap);

    proj_kernel<<<pg, 256>>>(Wo, bo, ap, out, nullptr, nullptr, x, gamma);
}

// round 5
// speedup vs baseline: 4.0808x; 1.2523x over previous
#include <cuda_runtime.h>
#include <cuda_bf16.h>
#include <math.h>
#include <stdint.h>

#define C_   256
#define HW_  4096
#define B_   2
#define NH_  8
#define DH_  32
#define LOG2E 1.4426950408889634f

// ---------------------------------------------------------------------------
// Scratch (no cudaMalloc):
//   g_xh/g_xl   : x transposed+split  [b][hw][c]
//   g_qh..g_vl  : q,k,v planes        [b][c][hw]
//   g_aoh/g_aol : attention out       [b][hw][c]
//   g_wh/g_wl   : 4 weight matrices   [wi][o][c]
// ---------------------------------------------------------------------------
__device__ __nv_bfloat16 g_xh[B_ * HW_ * C_];
__device__ __nv_bfloat16 g_xl[B_ * HW_ * C_];
__device__ __nv_bfloat16 g_qh[B_ * C_ * HW_];
__device__ __nv_bfloat16 g_ql[B_ * C_ * HW_];
__device__ __nv_bfloat16 g_kh[B_ * C_ * HW_];
__device__ __nv_bfloat16 g_kl[B_ * C_ * HW_];
__device__ __nv_bfloat16 g_vh[B_ * C_ * HW_];
__device__ __nv_bfloat16 g_vl[B_ * C_ * HW_];
__device__ __nv_bfloat16 g_aoh[B_ * HW_ * C_];
__device__ __nv_bfloat16 g_aol[B_ * HW_ * C_];
__device__ __nv_bfloat16 g_wh[4 * C_ * C_];
__device__ __nv_bfloat16 g_wl[4 * C_ * C_];
__device__ float g_maxk[B_ * NH_];

// ===========================================================================
// helpers
// ===========================================================================
__device__ __forceinline__ uint32_t smem_u32(const void* p) {
    uint32_t a;
    asm("{ .reg .u64 t; cvta.to.shared.u64 t, %1; cvt.u32.u64 %0, t; }"
        : "=r"(a) : "l"(p));
    return a;
}
__device__ __forceinline__ void cp16(uint32_t saddr, const void* gaddr) {
    asm volatile("cp.async.cg.shared.global [%0], [%1], 16;"
                 :: "r"(saddr), "l"(gaddr));
}
#define CP_COMMIT() asm volatile("cp.async.commit_group;")
#define CP_WAIT(N)  asm volatile("cp.async.wait_group %0;" :: "n"(N))

__device__ __forceinline__ void ldsm_x4(uint32_t a[4], uint32_t addr) {
    asm volatile("ldmatrix.sync.aligned.m8n8.x4.shared.b16 {%0,%1,%2,%3}, [%4];"
                 : "=r"(a[0]), "=r"(a[1]), "=r"(a[2]), "=r"(a[3]) : "r"(addr));
}
__device__ __forceinline__ void ldsm_x4_t(uint32_t a[4], uint32_t addr) {
    asm volatile("ldmatrix.sync.aligned.m8n8.x4.trans.shared.b16 {%0,%1,%2,%3}, [%4];"
                 : "=r"(a[0]), "=r"(a[1]), "=r"(a[2]), "=r"(a[3]) : "r"(addr));
}
__device__ __forceinline__ void mma_bf16(float c[4], const uint32_t a[4],
                                         uint32_t b0, uint32_t b1) {
    asm volatile("mma.sync.aligned.m16n8k16.row.col.f32.bf16.bf16.f32 "
                 "{%0,%1,%2,%3}, {%4,%5,%6,%7}, {%8,%9}, {%0,%1,%2,%3};"
                 : "+f"(c[0]), "+f"(c[1]), "+f"(c[2]), "+f"(c[3])
                 : "r"(a[0]), "r"(a[1]), "r"(a[2]), "r"(a[3]), "r"(b0), "r"(b1));
}
__device__ __forceinline__ float fexp2(float x) {
    float y; asm("ex2.approx.f32 %0, %1;" : "=f"(y) : "f"(x)); return y;
}
// pack (lo element, hi element) -> bf16x2 (first arg in low 16 bits)
__device__ __forceinline__ uint32_t packbf(float lo, float hi) {
    uint32_t u; asm("cvt.rn.bf16x2.f32 %0, %1, %2;" : "=r"(u) : "f"(hi), "f"(lo));
    return u;
}
__device__ __forceinline__ void split1(float f, __nv_bfloat16& h, __nv_bfloat16& l) {
    h = __float2bfloat16_rn(f);
    l = __float2bfloat16_rn(f - __bfloat162float(h));
}

// ===========================================================================
// Weight split: 4 x [256x256] fp32 -> bf16 hi/lo planes
// ===========================================================================
__global__ __launch_bounds__(256) void wsplit_kernel(
    const float* __restrict__ W0, const float* __restrict__ W1,
    const float* __restrict__ W2, const float* __restrict__ W3)
{
    const int wi = blockIdx.y;
    const float* W = (wi == 0) ? W0 : (wi == 1) ? W1 : (wi == 2) ? W2 : W3;
    const int idx = blockIdx.x * 256 + threadIdx.x;   // grid.x = 256
    __nv_bfloat16 h, l;
    split1(W[idx], h, l);
    g_wh[wi * C_ * C_ + idx] = h;
    g_wl[wi * C_ * C_ + idx] = l;
}

// ===========================================================================
// x transpose+split: [b][c][hw] fp32 -> [b][hw][c] bf16 hi/lo
// ===========================================================================
__global__ __launch_bounds__(256) void xsplit_kernel(const float* __restrict__ x)
{
    __shared__ float tile[32][33];
    const int hw0 = blockIdx.x << 5;
    const int c0  = blockIdx.y << 5;
    const int b   = blockIdx.z;
    const int tx = threadIdx.x, ty = threadIdx.y;   // (32, 8)
    #pragma unroll
    for (int yy = 0; yy < 4; yy++)
        tile[ty + 8 * yy][tx] =
            x[((size_t)b * C_ + c0 + ty + 8 * yy) * HW_ + hw0 + tx];
    __syncthreads();
    #pragma unroll
    for (int yy = 0; yy < 4; yy++) {
        const int hw = hw0 + ty + 8 * yy;
        const int c  = c0 + tx;
        __nv_bfloat16 h, l;
        split1(tile[tx][ty + 8 * yy], h, l);
        g_xh[((size_t)b * HW_ + hw) * C_ + c] = h;
        g_xl[((size_t)b * HW_ + hw) * C_ + c] = l;
    }
}

// ===========================================================================
// Tensor-core projection: dst[o][n] = sum_c W[o][c] * X[n][c] + bias[o]
//   A = W planes [o][c], B = X planes [n][c]; 3-term bf16 split, fp32 accum.
//   mode 0: write bf16 hi/lo planes [b][o][hw]
//   mode 1: write fp32 gamma*(acc+bias)+resid to dstf [b][o][hw]
// CTA tile 128(o) x 128(n); 8 warps = 4(oM) x 2(nN); warp tile 32x64.
// ===========================================================================
#define PJ_PLANE 10240          // 128 rows x 80B
#define PJ_BUF   40960          // 4 planes
#define PJ_SMEM  81920

__global__ __launch_bounds__(256) void proj_mma_kernel(
    const __nv_bfloat16* __restrict__ Wh, const __nv_bfloat16* __restrict__ Wl,
    const float* __restrict__ bias,
    const __nv_bfloat16* __restrict__ Xh, const __nv_bfloat16* __restrict__ Xl,
    __nv_bfloat16* __restrict__ dsth, __nv_bfloat16* __restrict__ dstl,
    float* __restrict__ dstf, const float* __restrict__ resid,
    const float* __restrict__ gamma, int mode)
{
    extern __shared__ char smem[];
    const uint32_t sb = smem_u32(smem);

    const int n0 = blockIdx.x << 7;
    const int m0 = blockIdx.y << 7;
    const int b  = blockIdx.z;
    const int t  = threadIdx.x;
    const int w  = t >> 5, lane = t & 31;
    const int wM = w & 3, wN = w >> 2;
    const int g = lane >> 2, tq = lane & 3;

    // cp.async mapping: 2048 cp16 per buffer fill, 8 per thread
    // idx: p = plane (0 Wh,1 Wl,2 Xh,3 Xl), row 0..127, chunk 0..3
    auto load_buf = [&](int kc, uint32_t bufo) {
        #pragma unroll
        for (int i = 0; i < 8; i++) {
            const int idx = t + (i << 8);
            const int p = idx >> 9;
            const int r = idx & 511;
            const int row = r >> 2, ch = r & 3;
            const __nv_bfloat16* src;
            if (p < 2) src = (p ? Wl : Wh) + (size_t)(m0 + row) * C_ + kc * 32 + ch * 8;
            else       src = (p == 3 ? Xl : Xh)
                           + ((size_t)b * HW_ + n0 + row) * C_ + kc * 32 + ch * 8;
            cp16(sb + bufo + p * PJ_PLANE + row * 80 + ch * 16, src);
        }
        CP_COMMIT();
    };

    load_buf(0, 0);

    float racc[2][8][4] = {};

    // non-trans ldsm lane addressing
    const int arow = (lane & 7) + ((lane >> 3) & 1) * 8;
    const int acol = ((lane >> 4) & 1) * 16;            // bytes (k half)
    const int brow = (lane & 7);
    const int bsel8  = ((lane >> 3) & 1) * 16;          // k-half bytes
    const int bsel16 = ((lane >> 4) & 1) * 8;           // n +8 rows (FIXED)

    for (int kc = 0; kc < 8; kc++) {
        const uint32_t bufC = (uint32_t)(kc & 1) * PJ_BUF;
        if (kc < 7) load_buf(kc + 1, (uint32_t)((kc + 1) & 1) * PJ_BUF);
        if (kc < 7) { CP_WAIT(1); } else { CP_WAIT(0); }
        __syncthreads();

        #pragma unroll
        for (int kk = 0; kk < 2; kk++) {
            uint32_t aW[2][2][4];   // [plane][mf][4]
            #pragma unroll
            for (int p = 0; p < 2; p++)
                #pragma unroll
                for (int mf = 0; mf < 2; mf++)
                    ldsm_x4(aW[p][mf],
                        sb + bufC + p * PJ_PLANE
                           + (wM * 32 + mf * 16 + arow) * 80 + kk * 32 + acol);

            #pragma unroll
            for (int jp = 0; jp < 4; jp++) {
                uint32_t bh4[4], bl4[4];
                // matrices: (n+0..7, k0-7), (n+0..7, k8-15),
                //           (n+8..15, k0-7), (n+8..15, k8-15)
                const uint32_t baddr = (wN * 64 + jp * 16 + bsel16 + brow) * 80
                                     + kk * 32 + bsel8;
                ldsm_x4(bh4, sb + bufC + 2 * PJ_PLANE + baddr);
                ldsm_x4(bl4, sb + bufC + 3 * PJ_PLANE + baddr);
                #pragma unroll
                for (int mf = 0; mf < 2; mf++) {
                    mma_bf16(racc[mf][2*jp],   aW[0][mf], bh4[0], bh4[1]);
                    mma_bf16(racc[mf][2*jp+1], aW[0][mf], bh4[2], bh4[3]);
                    mma_bf16(racc[mf][2*jp],   aW[1][mf], bh4[0], bh4[1]);
                    mma_bf16(racc[mf][2*jp+1], aW[1][mf], bh4[2], bh4[3]);
                    mma_bf16(racc[mf][2*jp],   aW[0][mf], bl4[0], bl4[1]);
                    mma_bf16(racc[mf][2*jp+1], aW[0][mf], bl4[2], bl4[3]);
                }
            }
        }
        __syncthreads();
    }

    // epilogue
    const float gm = (mode == 1) ? gamma[0] : 0.0f;
    #pragma unroll
    for (int mf = 0; mf < 2; mf++) {
        #pragma unroll
        for (int half = 0; half < 2; half++) {
            const int o = m0 + wM * 32 + mf * 16 + g + half * 8;
            const float bia = bias[o];
            #pragma unroll
            for (int j = 0; j < 8; j++) {
                const int n = n0 + wN * 64 + j * 8 + tq * 2;
                const size_t idx = ((size_t)b * C_ + o) * HW_ + n;
                const float v0 = racc[mf][j][half * 2 + 0] + bia;
                const float v1 = racc[mf][j][half * 2 + 1] + bia;
                if (mode == 0) {
                    __nv_bfloat16 h0, l0, h1, l1;
                    split1(v0, h0, l0); split1(v1, h1, l1);
                    *(__nv_bfloat162*)&dsth[idx] = __nv_bfloat162(h0, h1);
                    *(__nv_bfloat162*)&dstl[idx] = __nv_bfloat162(l0, l1);
                } else {
                    const float2 rr = *(const float2*)&resid[idx];
                    float2 r;
                    r.x = gm * v0 + rr.x;
                    r.y = gm * v1 + rr.y;
                    *(float2*)&dstf[idx] = r;
                }
            }
        }
    }
}

// ===========================================================================
// maxk: reset + parallel atomic max of ||k_m|| per (b,h)
// ===========================================================================
__global__ void maxk_reset_kernel() {
    if (threadIdx.x < B_ * NH_) g_maxk[threadIdx.x] = 0.0f;
}
__global__ __launch_bounds__(256) void maxk_kernel(
    const __nv_bfloat16* __restrict__ kh, const __nv_bfloat16* __restrict__ kl)
{
    const int bh = blockIdx.x;
    const int m = blockIdx.y * 256 + threadIdx.x;
    const size_t base = (size_t)bh * DH_ * HW_;
    float s = 0.0f;
    #pragma unroll
    for (int d = 0; d < DH_; d++) {
        const size_t idx = base + (size_t)d * HW_ + m;
        const float v = __bfloat162float(kh[idx]) + __bfloat162float(kl[idx]);
        s += v * v;
    }
    s = fmaxf(s, __shfl_xor_sync(0xffffffffu, s, 1));
    s = fmaxf(s, __shfl_xor_sync(0xffffffffu, s, 2));
    s = fmaxf(s, __shfl_xor_sync(0xffffffffu, s, 4));
    s = fmaxf(s, __shfl_xor_sync(0xffffffffu, s, 8));
    s = fmaxf(s, __shfl_xor_sync(0xffffffffu, s, 16));
    if ((threadIdx.x & 31) == 0)
        atomicMax((unsigned int*)&g_maxk[bh], __float_as_uint(sqrtf(s)));
}

// ===========================================================================
// HMMA flash attention v2: 256-query CTA, 8 warps x 32 queries, Bc = 64.
// Q/K/V planes [c][hw] d-major. Output bf16 hi/lo [b][hw][c].
// ===========================================================================
#define AQ_OFF 0
#define AQ_ROW 528                                   // 256 q *2B + 16 pad
#define AQ_PLANE (32 * AQ_ROW)                       // 16896
#define AK_OFF (AQ_OFF + 2 * AQ_PLANE)               // 33792
#define AKV_ROW 144                                  // 64 m *2B + 16 pad
#define AKV_PLANE (32 * AKV_ROW)                     // 4608
#define AKV_BUF (2 * AKV_PLANE)                      // 9216
#define AV_OFF (AK_OFF + 2 * AKV_BUF)                // 52224
#define AMH_OFF (AV_OFF + 2 * AKV_BUF)               // 70656
#define AT_SMEM (AMH_OFF + 256 * 4)                  // 71680

__global__ __launch_bounds__(256, 1) void attn_mma_kernel(
    const __nv_bfloat16* __restrict__ qh, const __nv_bfloat16* __restrict__ ql,
    const __nv_bfloat16* __restrict__ kh, const __nv_bfloat16* __restrict__ kl,
    const __nv_bfloat16* __restrict__ vh, const __nv_bfloat16* __restrict__ vl,
    __nv_bfloat16* __restrict__ oh, __nv_bfloat16* __restrict__ ol)
{
    extern __shared__ char smem[];
    const uint32_t sb = smem_u32(smem);
    float* mhat = (float*)(smem + AMH_OFF);

    const int bh = blockIdx.y;
    const int q0 = blockIdx.x << 8;                  // 256-query tiles
    const int t  = threadIdx.x;
    const int w  = t >> 5;
    const int lane = t & 31;
    const int g = lane >> 2, tq = lane & 3;
    const size_t base = (size_t)bh * DH_ * HW_;
    const int b = bh >> 3, hh = bh & 7;

    const __nv_bfloat16* kvp[4] = { kh + base, kl + base, vh + base, vl + base };

    // ---- issue Q (2 planes, 2048 cp16) + KV iter0 (1024 cp16)
    {
        const __nv_bfloat16* qp[2] = { qh + base, ql + base };
        #pragma unroll
        for (int i = 0; i < 8; i++) {
            const int idx = t + (i << 8);
            const int p = idx >> 10;
            const int r = idx & 1023;
            const int d = r >> 5, ch = r & 31;
            cp16(sb + AQ_OFF + p * AQ_PLANE + d * AQ_ROW + ch * 16,
                 qp[p] + (size_t)d * HW_ + q0 + ch * 8);
        }
        #pragma unroll
        for (int i = 0; i < 4; i++) {
            const int idx = t + (i << 8);
            const int p4 = idx >> 8;
            const int r = idx & 255;
            const int d = r >> 3, ch = r & 7;
            const uint32_t so = (p4 < 2 ? AK_OFF : AV_OFF) + (p4 & 1) * AKV_PLANE;
            cp16(sb + so + d * AKV_ROW + ch * 16,
                 kvp[p4] + (size_t)d * HW_ + ch * 8);
        }
        CP_COMMIT();
    }
    CP_WAIT(0);
    __syncthreads();

    // ---- mhat (pre-scaled by LOG2E)
    {
        float s = 0.0f;
        #pragma unroll
        for (int d = 0; d < DH_; d++) {
            const __nv_bfloat16* r0 =
                (const __nv_bfloat16*)(smem + AQ_OFF + d * AQ_ROW);
            const __nv_bfloat16* r1 =
                (const __nv_bfloat16*)(smem + AQ_OFF + AQ_PLANE + d * AQ_ROW);
            const float f = __bfloat162float(r0[t]) + __bfloat162float(r1[t]);
            s += f * f;
        }
        mhat[t] = sqrtf(s) * g_maxk[bh] * LOG2E;
    }

    // ---- Q A-fragments (trans): aQ[plane][kstep s][mfrag][4]
    uint32_t aQ[2][2][2][4];
    {
        const int qrow = (lane & 7) + ((lane >> 4) << 3);      // d
        const int qsel = ((lane >> 3) & 1) << 3;               // q +8
        #pragma unroll
        for (int p = 0; p < 2; p++)
            #pragma unroll
            for (int s = 0; s < 2; s++)
                #pragma unroll
                for (int mf = 0; mf < 2; mf++)
                    ldsm_x4_t(aQ[p][s][mf],
                        sb + AQ_OFF + p * AQ_PLANE
                           + ((s << 4) + qrow) * AQ_ROW
                           + (w * 32 + mf * 16 + qsel) * 2);
    }
    __syncthreads();   // mhat visible

    float mh[2][2];
    #pragma unroll
    for (int mf = 0; mf < 2; mf++)
        #pragma unroll
        for (int h = 0; h < 2; h++)
            mh[mf][h] = mhat[w * 32 + mf * 16 + g + h * 8];

    float oacc[2][4][4] = {};
    float Lac[2][2] = {};

    // trans ldsm lane parts (K), non-trans (V)
    const int kRowD = (lane & 7) + ((lane >> 4) << 3);       // d row (trans)
    const int kColB = ((lane >> 3) & 1) * 16;                // m +8 bytes
    const int vRowP = (lane & 7) + (((lane >> 4) & 1) << 3); // d row (non-trans)
    const int vColB = ((lane >> 3) & 1) * 16;                // m +8 bytes

    for (int i = 0; i < 64; i++) {
        const uint32_t bufC = (uint32_t)(i & 1) * AKV_BUF;
        if (i < 63) {
            const int m0n = (i + 1) << 6;
            const uint32_t bufN = (uint32_t)((i + 1) & 1) * AKV_BUF;
            #pragma unroll
            for (int u = 0; u < 4; u++) {
                const int idx = t + (u << 8);
                const int p4 = idx >> 8;
                const int r = idx & 255;
                const int d = r >> 3, ch = r & 7;
                const uint32_t so = (p4 < 2 ? AK_OFF : AV_OFF)
                                  + (p4 & 1) * AKV_PLANE + bufN;
                cp16(sb + so + d * AKV_ROW + ch * 16,
                     kvp[p4] + (size_t)d * HW_ + m0n + ch * 8);
            }
            CP_COMMIT();
            CP_WAIT(1);
        } else {
            CP_WAIT(0);
        }
        __syncthreads();

        // ---- S = Q K^T, sacc[mfrag][8 nblk][4]
        float sacc[2][8][4] = {};
        #pragma unroll
        for (int s = 0; s < 2; s++) {
            #pragma unroll
            for (int jp = 0; jp < 4; jp++) {
                uint32_t kh4[4], kl4[4];
                const uint32_t ka = bufC + ((s << 4) + kRowD) * AKV_ROW
                                  + jp * 32 + kColB;
                ldsm_x4_t(kh4, sb + AK_OFF + ka);
                ldsm_x4_t(kl4, sb + AK_OFF + AKV_PLANE + ka);
                #pragma unroll
                for (int mf = 0; mf < 2; mf++) {
                    mma_bf16(sacc[mf][2*jp],   aQ[0][s][mf], kh4[0], kh4[2]);
                    mma_bf16(sacc[mf][2*jp+1], aQ[0][s][mf], kh4[1], kh4[3]);
                    mma_bf16(sacc[mf][2*jp],   aQ[1][s][mf], kh4[0], kh4[2]);
                    mma_bf16(sacc[mf][2*jp+1], aQ[1][s][mf], kh4[1], kh4[3]);
                    mma_bf16(sacc[mf][2*jp],   aQ[0][s][mf], kl4[0], kl4[2]);
                    mma_bf16(sacc[mf][2*jp+1], aQ[0][s][mf], kl4[1], kl4[3]);
                }
            }
        }

        // ---- softmax (fixed bound), P in registers
        #pragma unroll
        for (int mf = 0; mf < 2; mf++)
            #pragma unroll
            for (int j = 0; j < 8; j++) {
                sacc[mf][j][0] = fexp2(fmaf(sacc[mf][j][0], LOG2E, -mh[mf][0]));
                sacc[mf][j][1] = fexp2(fmaf(sacc[mf][j][1], LOG2E, -mh[mf][0]));
                sacc[mf][j][2] = fexp2(fmaf(sacc[mf][j][2], LOG2E, -mh[mf][1]));
                sacc[mf][j][3] = fexp2(fmaf(sacc[mf][j][3], LOG2E, -mh[mf][1]));
                Lac[mf][0] += sacc[mf][j][0] + sacc[mf][j][1];
                Lac[mf][1] += sacc[mf][j][2] + sacc[mf][j][3];
            }

        // ---- O += P V
        #pragma unroll
        for (int ks = 0; ks < 4; ks++) {
            uint32_t ah[2][4], al[2][4];
            #pragma unroll
            for (int mf = 0; mf < 2; mf++) {
                const float* p0 = sacc[mf][2*ks];
                const float* p1 = sacc[mf][2*ks+1];
                ah[mf][0] = packbf(p0[0], p0[1]);
                ah[mf][1] = packbf(p0[2], p0[3]);
                ah[mf][2] = packbf(p1[0], p1[1]);
                ah[mf][3] = packbf(p1[2], p1[3]);
                #pragma unroll
                for (int e = 0; e < 4; e++) {
                    const float* pp = (e < 2) ? p0 : p1;
                    const int bi = (e & 1) << 1;
                    const float hx = __uint_as_float(ah[mf][e] << 16);
                    const float hy = __uint_as_float(ah[mf][e] & 0xffff0000u);
                    al[mf][e] = packbf(pp[bi] - hx, pp[bi + 1] - hy);
                }
            }
            #pragma unroll
            for (int jp = 0; jp < 2; jp++) {
                uint32_t vh4[4], vl4[4];
                const uint32_t va = bufC + (jp * 16 + vRowP) * AKV_ROW
                                  + ks * 32 + vColB;
                ldsm_x4(vh4, sb + AV_OFF + va);
                ldsm_x4(vl4, sb + AV_OFF + AKV_PLANE + va);
                #pragma unroll
                for (int mf = 0; mf < 2; mf++) {
                    mma_bf16(oacc[mf][2*jp],   ah[mf], vh4[0], vh4[1]);
                    mma_bf16(oacc[mf][2*jp+1], ah[mf], vh4[2], vh4[3]);
                    mma_bf16(oacc[mf][2*jp],   al[mf], vh4[0], vh4[1]);
                    mma_bf16(oacc[mf][2*jp+1], al[mf], vh4[2], vh4[3]);
                    mma_bf16(oacc[mf][2*jp],   ah[mf], vl4[0], vl4[1]);
                    mma_bf16(oacc[mf][2*jp+1], ah[mf], vl4[2], vl4[3]);
                }
            }
        }
        __syncthreads();
    }

    // ---- epilogue: quad-reduce L, normalize, split, store [b][hw][c]
    #pragma unroll
    for (int mf = 0; mf < 2; mf++)
        #pragma unroll
        for (int h = 0; h < 2; h++) {
            Lac[mf][h] += __shfl_xor_sync(0xffffffffu, Lac[mf][h], 1);
            Lac[mf][h] += __shfl_xor_sync(0xffffffffu, Lac[mf][h], 2);
            Lac[mf][h] = 1.0f / Lac[mf][h];
        }

    #pragma unroll
    for (int mf = 0; mf < 2; mf++)
        #pragma unroll
        for (int h = 0; h < 2; h++) {
            const int hw = q0 + w * 32 + mf * 16 + g + h * 8;
            #pragma unroll
            for (int dj = 0; dj < 4; dj++) {
                const int d = 8 * dj + tq * 2;
                const float v0 = oacc[mf][dj][h * 2 + 0] * Lac[mf][h];
                const float v1 = oacc[mf][dj][h * 2 + 1] * Lac[mf][h];
                __nv_bfloat16 h0, l0, h1, l1;
                split1(v0, h0, l0); split1(v1, h1, l1);
                const size_t idx = ((size_t)b * HW_ + hw) * C_ + hh * 32 + d;
                *(__nv_bfloat162*)&oh[idx] = __nv_bfloat162(h0, h1);
                *(__nv_bfloat162*)&ol[idx] = __nv_bfloat162(l0, l1);
            }
        }
}

// ===========================================================================
extern "C" void kernel_launch(void* const* d_in, const int* in_sizes, int n_in,
                              void* d_out, int out_size)
{
    const float* x     = (const float*)d_in[0];
    const float* Wq    = (const float*)d_in[1];
    const float* bq    = (const float*)d_in[2];
    const float* Wk    = (const float*)d_in[3];
    const float* bk    = (const float*)d_in[4];
    const float* Wv    = (const float*)d_in[5];
    const float* bv    = (const float*)d_in[6];
    const float* Wo    = (const float*)d_in[7];
    const float* bo    = (const float*)d_in[8];
    const float* gamma = (const float*)d_in[9];
    float* out = (float*)d_out;

    __nv_bfloat16 *xh, *xl, *qhp, *qlp, *khp, *klp, *vhp, *vlp, *aoh, *aol, *wh, *wl;
    cudaGetSymbolAddress((void**)&xh,  g_xh);
    cudaGetSymbolAddress((void**)&xl,  g_xl);
    cudaGetSymbolAddress((void**)&qhp, g_qh);
    cudaGetSymbolAddress((void**)&qlp, g_ql);
    cudaGetSymbolAddress((void**)&khp, g_kh);
    cudaGetSymbolAddress((void**)&klp, g_kl);
    cudaGetSymbolAddress((void**)&vhp, g_vh);
    cudaGetSymbolAddress((void**)&vlp, g_vl);
    cudaGetSymbolAddress((void**)&aoh, g_aoh);
    cudaGetSymbolAddress((void**)&aol, g_aol);
    cudaGetSymbolAddress((void**)&wh,  g_wh);
    cudaGetSymbolAddress((void**)&wl,  g_wl);

    cudaFuncSetAttribute(proj_mma_kernel,
                         cudaFuncAttributeMaxDynamicSharedMemorySize, PJ_SMEM);
    cudaFuncSetAttribute(attn_mma_kernel,
                         cudaFuncAttributeMaxDynamicSharedMemorySize, AT_SMEM);

    wsplit_kernel<<<dim3(256, 4), 256>>>(Wq, Wk, Wv, Wo);
    xsplit_kernel<<<dim3(HW_ / 32, C_ / 32, B_), dim3(32, 8)>>>(x);

    dim3 pg(HW_ / 128, C_ / 128, B_);   // 32 x 2 x 2
    proj_mma_kernel<<<pg, 256, PJ_SMEM>>>(wh + 0 * C_ * C_, wl + 0 * C_ * C_, bq,
                                          xh, xl, qhp, qlp, nullptr, nullptr, nullptr, 0);
    proj_mma_kernel<<<pg, 256, PJ_SMEM>>>(wh + 1 * C_ * C_, wl + 1 * C_ * C_, bk,
                                          xh, xl, khp, klp, nullptr, nullptr, nullptr, 0);
    proj_mma_kernel<<<pg, 256, PJ_SMEM>>>(wh + 2 * C_ * C_, wl + 2 * C_ * C_, bv,
                                          xh, xl, vhp, vlp, nullptr, nullptr, nullptr, 0);

    maxk_reset_kernel<<<1, 32>>>();
    maxk_kernel<<<dim3(B_ * NH_, HW_ / 256), 256>>>(khp, klp);

    dim3 ag(HW_ / 256, B_ * NH_);       // 16 x 16
    attn_mma_kernel<<<ag, 256, AT_SMEM>>>(qhp, qlp, khp, klp, vhp, vlp, aoh, aol);

    proj_mma_kernel<<<pg, 256, PJ_SMEM>>>(wh + 3 * C_ * C_, wl + 3 * C_ * C_, bo,
                                          aoh, aol, nullptr, nullptr, out, x, gamma, 1);
}